// round 1
// baseline (speedup 1.0000x reference)
#include <cuda_runtime.h>

// Grid: 128^3 cells, cell c = (bin + 64), layout idx = x + 128*y + 16384*z
// Each cell: float4 {sum_x, sum_y, sum_z, count}
#define D    128
#define D3   (128*128*128)
#define OFF  64
#define NMAX 200704

__device__ float4 g_grid0[D3];   // scatter target / conv ping
__device__ float4 g_grid1[D3];   // conv pong / gather source
__device__ float  g_Xbuf[2][NMAX * 3];
__device__ unsigned g_maxd2_bits;
__device__ int g_done;

// ---------------------------------------------------------------- zero
__global__ void zero_kernel(int reset_done) {
    int i = blockIdx.x * blockDim.x + threadIdx.x;
    if (i < D3) g_grid0[i] = make_float4(0.f, 0.f, 0.f, 0.f);
    if (i == 0) {
        g_maxd2_bits = 0u;
        if (reset_done) g_done = 0;
    }
}

// ---------------------------------------------------------------- scatter
__device__ __forceinline__ int bin_of(float v) {
    // match jnp:  (X / 0.1f).astype(int32)  == trunc toward zero, IEEE RN divide
    int b = (int)__fdiv_rn(v, 0.1f);
    b += OFF;
    return min(max(b, 0), D - 1);
}

__global__ void scatter_kernel(const float* __restrict__ Xext, int srcSel, int n) {
    const float* X = (srcSel < 0) ? Xext : g_Xbuf[srcSel];
    int i = blockIdx.x * blockDim.x + threadIdx.x;
    if (i >= n) return;
    float x = X[3 * i + 0];
    float y = X[3 * i + 1];
    float z = X[3 * i + 2];
    int cell = bin_of(x) + (bin_of(y) << 7) + (bin_of(z) << 14);
    float4* c = &g_grid0[cell];
    atomicAdd(&c->x, x);
    atomicAdd(&c->y, y);
    atomicAdd(&c->z, z);
    atomicAdd(&c->w, 1.0f);
}

// ---------------------------------------------------------------- separable conv
// weights [1,2,3,2,1] per axis (box3 * box3). Tiles: full line (128) x chunk 16.
// 2048 float4 = 32KB static smem per block. 1024 blocks per pass.

__global__ __launch_bounds__(256) void convx_kernel() {   // g_grid0 -> g_grid1
    __shared__ float4 s[2048];
    int z  = blockIdx.x >> 3;
    int y0 = (blockIdx.x & 7) << 4;       // 16-row chunk
    int base = (z << 14) + (y0 << 7);
    for (int i = threadIdx.x; i < 2048; i += 256)
        s[i] = g_grid0[base + i];         // i = yloc*128 + x, contiguous
    __syncthreads();
    const float W[5] = {1.f, 2.f, 3.f, 2.f, 1.f};
    for (int i = threadIdx.x; i < 2048; i += 256) {
        int x = i & 127;
        int yrow = i & ~127;
        float4 a = make_float4(0.f, 0.f, 0.f, 0.f);
#pragma unroll
        for (int d = 0; d < 5; d++) {
            int xs = min(max(x + d - 2, 0), D - 1);  // clamp: edge cells are 0 anyway
            float4 v = s[yrow + xs];
            float w = W[d];
            a.x += w * v.x; a.y += w * v.y; a.z += w * v.z; a.w += w * v.w;
        }
        g_grid1[base + i] = a;
    }
}

__global__ __launch_bounds__(256) void convy_kernel() {   // g_grid1 -> g_grid0
    __shared__ float4 s[2048];            // [y][xl16]
    int z  = blockIdx.x >> 3;
    int x0 = (blockIdx.x & 7) << 4;
    int base = (z << 14) + x0;
    for (int i = threadIdx.x; i < 2048; i += 256) {
        int yy = i >> 4, xl = i & 15;
        s[i] = g_grid1[base + (yy << 7) + xl];
    }
    __syncthreads();
    const float W[5] = {1.f, 2.f, 3.f, 2.f, 1.f};
    for (int i = threadIdx.x; i < 2048; i += 256) {
        int yy = i >> 4, xl = i & 15;
        float4 a = make_float4(0.f, 0.f, 0.f, 0.f);
#pragma unroll
        for (int d = 0; d < 5; d++) {
            int ys = min(max(yy + d - 2, 0), D - 1);
            float4 v = s[(ys << 4) + xl];
            float w = W[d];
            a.x += w * v.x; a.y += w * v.y; a.z += w * v.z; a.w += w * v.w;
        }
        g_grid0[base + (yy << 7) + xl] = a;
    }
}

__global__ __launch_bounds__(256) void convz_kernel() {   // g_grid0 -> g_grid1
    __shared__ float4 s[2048];            // [z][xl16]
    int y  = blockIdx.x >> 3;
    int x0 = (blockIdx.x & 7) << 4;
    int base = (y << 7) + x0;
    for (int i = threadIdx.x; i < 2048; i += 256) {
        int zz = i >> 4, xl = i & 15;
        s[i] = g_grid0[base + (zz << 14) + xl];
    }
    __syncthreads();
    const float W[5] = {1.f, 2.f, 3.f, 2.f, 1.f};
    for (int i = threadIdx.x; i < 2048; i += 256) {
        int zz = i >> 4, xl = i & 15;
        float4 a = make_float4(0.f, 0.f, 0.f, 0.f);
#pragma unroll
        for (int d = 0; d < 5; d++) {
            int zs = min(max(zz + d - 2, 0), D - 1);
            float4 v = s[(zs << 4) + xl];
            float w = W[d];
            a.x += w * v.x; a.y += w * v.y; a.z += w * v.z; a.w += w * v.w;
        }
        g_grid1[base + (zz << 14) + xl] = a;
    }
}

// ---------------------------------------------------------------- gather
__global__ void gather_kernel(const float* __restrict__ Xext, int srcSel,
                              float* __restrict__ Oext, int dstSel, int n) {
    const float* X = (srcSel < 0) ? Xext : g_Xbuf[srcSel];
    float* Y = (dstSel < 0) ? Oext : g_Xbuf[dstSel];
    int i = blockIdx.x * blockDim.x + threadIdx.x;
    float d2 = 0.f;
    if (i < n) {
        float x = X[3 * i + 0];
        float y = X[3 * i + 1];
        float z = X[3 * i + 2];
        int cell = bin_of(x) + (bin_of(y) << 7) + (bin_of(z) << 14);
        float4 t = g_grid1[cell];
        float nx = __fdiv_rn(t.x, t.w);
        float ny = __fdiv_rn(t.y, t.w);
        float nz = __fdiv_rn(t.z, t.w);
        if (g_done) { nx = x; ny = y; nz = z; }
        Y[3 * i + 0] = nx;
        Y[3 * i + 1] = ny;
        Y[3 * i + 2] = nz;
        float dx = nx - x, dy = ny - y, dz = nz - z;
        d2 = dx * dx + dy * dy + dz * dz;
    }
#pragma unroll
    for (int o = 16; o > 0; o >>= 1)
        d2 = fmaxf(d2, __shfl_xor_sync(0xFFFFFFFFu, d2, o));
    if ((threadIdx.x & 31) == 0)
        atomicMax(&g_maxd2_bits, __float_as_uint(d2));
}

__global__ void check_kernel() {
    // max ||Xn - Xc|| <= 1e-3  <=>  max d2 <= 1e-6
    if (__uint_as_float(g_maxd2_bits) <= 1e-6f) g_done = 1;
}

// ---------------------------------------------------------------- launch
extern "C" void kernel_launch(void* const* d_in, const int* in_sizes, int n_in,
                              void* d_out, int out_size) {
    const float* Xin = (const float*)d_in[0];
    float* Out = (float*)d_out;
    int n = in_sizes[0] / 3;

    int pblocks = (n + 255) / 256;
    // ping-pong: step s reads src[s], writes dst[s]
    int srcSel[5] = {-1, 0, 1, 0, 1};
    int dstSel[5] = { 0, 1, 0, 1, -1};

    for (int s = 0; s < 5; s++) {
        zero_kernel<<<D3 / 512, 512>>>(s == 0);
        scatter_kernel<<<pblocks, 256>>>(Xin, srcSel[s], n);
        convx_kernel<<<1024, 256>>>();
        convy_kernel<<<1024, 256>>>();
        convz_kernel<<<1024, 256>>>();
        gather_kernel<<<pblocks, 256>>>(Xin, srcSel[s], Out, dstSel[s], n);
        check_kernel<<<1, 1>>>();
    }
}

// round 2
// speedup vs baseline: 1.3172x; 1.3172x over previous
#include <cuda_runtime.h>

// Grid: 128^3 cells, cell = (bin+64), idx = x + 128*y + 16384*z
// Each cell: float4 {sum_x, sum_y, sum_z, count}
#define D    128
#define D3   (128*128*128)
#define OFF  64
#define NMAX 200704

__device__ float4 g_grid0[D3];   // scatter target (zeroed back by gather)
__device__ float4 g_grid1[D3];   // conv output / gather source
__device__ float  g_Xbuf[2][NMAX * 3];
__device__ unsigned g_maxd2_bits;
__device__ int g_done;

// ---------------------------------------------------------------- helpers
__device__ __forceinline__ int bin_of(float v) {
    // match jnp: (X / 0.1f).astype(int32) == IEEE RN divide, trunc toward zero
    int b = (int)__fdiv_rn(v, 0.1f);
    b += OFF;
    return min(max(b, 0), D - 1);
}

__device__ __forceinline__ void fma4(float4& a, float w, const float4 v) {
    a.x += w * v.x; a.y += w * v.y; a.z += w * v.z; a.w += w * v.w;
}

// ---------------------------------------------------------------- scatter (+ convergence check)
__global__ void scatter_kernel(const float* __restrict__ Xext, int srcSel, int n, int first) {
    if (blockIdx.x == 0 && threadIdx.x == 0) {
        // fold check_kernel here: uses previous step's max displacement^2
        if (first) g_done = 0;
        else if (__uint_as_float(g_maxd2_bits) <= 1e-6f) g_done = 1;
        g_maxd2_bits = 0u;
    }
    const float* X = (srcSel < 0) ? Xext : g_Xbuf[srcSel];
    int i = blockIdx.x * blockDim.x + threadIdx.x;
    if (i >= n) return;
    float x = X[3 * i + 0];
    float y = X[3 * i + 1];
    float z = X[3 * i + 2];
    int cell = bin_of(x) + (bin_of(y) << 7) + (bin_of(z) << 14);
    float4* c = &g_grid0[cell];
    atomicAdd(&c->x, x);
    atomicAdd(&c->y, y);
    atomicAdd(&c->z, z);
    atomicAdd(&c->w, 1.0f);
}

// ---------------------------------------------------------------- fused 3D separable conv
// weights [1,2,3,2,1] per axis. Block: x=0..127 (full), 8 y-rows, 16 z-slices.
// Per slice: load 12 rows (y halo 2) -> smem raw, x-filter -> smem xf,
// y-filter -> register ring of 5, output z-filtered slice z-2.
// grid0 -> grid1. 128 blocks x 1024 threads.

__device__ __forceinline__ void load_slice(int zc, int x, int r, int y0,
                                           float4& a, float4& b) {
    int zoff = (min(max(zc, 0), D - 1)) << 14;
    int ya = min(max(y0 + r - 2, 0), D - 1);
    a = g_grid0[x + (ya << 7) + zoff];
    if (r < 4) {
        int yb = min(max(y0 + r + 6, 0), D - 1);
        b = g_grid0[x + (yb << 7) + zoff];
    }
}

__global__ __launch_bounds__(1024) void conv3d_kernel() {
    __shared__ float4 raw[12][D];
    __shared__ float4 xf[12][D];

    int x = threadIdx.x & 127;
    int r = threadIdx.x >> 7;            // 0..7
    int y0 = (blockIdx.x & 15) << 3;     // 16 y-tiles of 8
    int z0 = (blockIdx.x >> 4) << 4;     // 8 z-segments of 16

    const float W0 = 1.f, W1 = 2.f, W2 = 3.f, W3 = 2.f, W4 = 1.f;

    float4 r0, r1, r2, r3, r4;           // z ring
    r0 = r1 = r2 = r3 = r4 = make_float4(0.f, 0.f, 0.f, 0.f);

    float4 pa, pb;                       // prefetch regs
    load_slice(z0 - 2, x, r, y0, pa, pb);

#pragma unroll 1
    for (int zi = 0; zi < 20; zi++) {
        int zc = z0 - 2 + zi;
        raw[r][x] = pa;
        if (r < 4) raw[r + 8][x] = pb;
        __syncthreads();

        if (zi < 19) load_slice(zc + 1, x, r, y0, pa, pb);  // overlap with compute

        // x-filter: rows r and r+8 (if r<4)
        {
            int xm2 = max(x - 2, 0), xm1 = max(x - 1, 0);
            int xp1 = min(x + 1, D - 1), xp2 = min(x + 2, D - 1);
            float4 a = make_float4(0.f, 0.f, 0.f, 0.f);
            fma4(a, W0, raw[r][xm2]); fma4(a, W1, raw[r][xm1]);
            fma4(a, W2, raw[r][x]);   fma4(a, W3, raw[r][xp1]);
            fma4(a, W4, raw[r][xp2]);
            xf[r][x] = a;
            if (r < 4) {
                float4 b = make_float4(0.f, 0.f, 0.f, 0.f);
                fma4(b, W0, raw[r + 8][xm2]); fma4(b, W1, raw[r + 8][xm1]);
                fma4(b, W2, raw[r + 8][x]);   fma4(b, W3, raw[r + 8][xp1]);
                fma4(b, W4, raw[r + 8][xp2]);
                xf[r + 8][x] = b;
            }
        }
        __syncthreads();

        // y-filter for core row (global y = y0 + r, raw-coord row r+2)
        float4 a = make_float4(0.f, 0.f, 0.f, 0.f);
        fma4(a, W0, xf[r + 0][x]);
        fma4(a, W1, xf[r + 1][x]);
        fma4(a, W2, xf[r + 2][x]);
        fma4(a, W3, xf[r + 3][x]);
        fma4(a, W4, xf[r + 4][x]);

        // shift z ring
        r0 = r1; r1 = r2; r2 = r3; r3 = r4; r4 = a;

        if (zi >= 4) {
            int zo = zc - 2;             // z0 .. z0+15
            float4 o;
            o.x = r0.x + 2.f * r1.x + 3.f * r2.x + 2.f * r3.x + r4.x;
            o.y = r0.y + 2.f * r1.y + 3.f * r2.y + 2.f * r3.y + r4.y;
            o.z = r0.z + 2.f * r1.z + 3.f * r2.z + 2.f * r3.z + r4.z;
            o.w = r0.w + 2.f * r1.w + 3.f * r2.w + 2.f * r3.w + r4.w;
            g_grid1[x + ((y0 + r) << 7) + (zo << 14)] = o;
        }
        // no third sync needed: next raw store races only with xf reads (disjoint)
    }
}

// ---------------------------------------------------------------- gather (+ zero grid0)
__global__ void gather_kernel(const float* __restrict__ Xext, int srcSel,
                              float* __restrict__ Oext, int dstSel, int n) {
    const float* X = (srcSel < 0) ? Xext : g_Xbuf[srcSel];
    float* Y = (dstSel < 0) ? Oext : g_Xbuf[dstSel];
    int i = blockIdx.x * blockDim.x + threadIdx.x;
    float d2 = 0.f;
    if (i < n) {
        float x = X[3 * i + 0];
        float y = X[3 * i + 1];
        float z = X[3 * i + 2];
        int cell = bin_of(x) + (bin_of(y) << 7) + (bin_of(z) << 14);
        float4 t = g_grid1[cell];
        // zero grid0 at this cell (exactly the cells scatter touched this step);
        // keeps grid0 all-zero at step/replay boundaries without a 32MB memset
        g_grid0[cell] = make_float4(0.f, 0.f, 0.f, 0.f);
        float nx = __fdiv_rn(t.x, t.w);
        float ny = __fdiv_rn(t.y, t.w);
        float nz = __fdiv_rn(t.z, t.w);
        if (g_done) { nx = x; ny = y; nz = z; }
        Y[3 * i + 0] = nx;
        Y[3 * i + 1] = ny;
        Y[3 * i + 2] = nz;
        float dx = nx - x, dy = ny - y, dz = nz - z;
        d2 = dx * dx + dy * dy + dz * dz;
    }
#pragma unroll
    for (int o = 16; o > 0; o >>= 1)
        d2 = fmaxf(d2, __shfl_xor_sync(0xFFFFFFFFu, d2, o));
    if ((threadIdx.x & 31) == 0)
        atomicMax(&g_maxd2_bits, __float_as_uint(d2));
}

// ---------------------------------------------------------------- launch
extern "C" void kernel_launch(void* const* d_in, const int* in_sizes, int n_in,
                              void* d_out, int out_size) {
    const float* Xin = (const float*)d_in[0];
    float* Out = (float*)d_out;
    int n = in_sizes[0] / 3;

    int pblocks = (n + 255) / 256;
    int srcSel[5] = {-1, 0, 1, 0, 1};
    int dstSel[5] = { 0, 1, 0, 1, -1};

    for (int s = 0; s < 5; s++) {
        scatter_kernel<<<pblocks, 256>>>(Xin, srcSel[s], n, s == 0);
        conv3d_kernel<<<128, 1024>>>();
        gather_kernel<<<pblocks, 256>>>(Xin, srcSel[s], Out, dstSel[s], n);
    }
}